// round 2
// baseline (speedup 1.0000x reference)
#include <cuda_runtime.h>
#include <math.h>

#define BB 8
#define CC 512
#define TT 4096

// Scratch: G, H, dots, attn, M (each B*C*C) + s,u,w,r vectors. ~42MB.
static __device__ float g_scr[5u*BB*CC*CC + 4u*BB*CC];

// ---------------- f32x2 packed-FMA helpers (2x fp32 throughput on sm_103a) ---
__device__ __forceinline__ unsigned long long pk2(float lo, float hi){
    unsigned long long r;
    asm("mov.b64 %0, {%1,%2};" : "=l"(r) : "f"(lo), "f"(hi));
    return r;
}
__device__ __forceinline__ void upk2(unsigned long long v, float &lo, float &hi){
    asm("mov.b64 {%0,%1}, %2;" : "=f"(lo), "=f"(hi) : "l"(v));
}
__device__ __forceinline__ void fma2(unsigned long long &d, unsigned long long a, unsigned long long b){
    asm("fma.rn.f32x2 %0, %1, %2, %0;" : "+l"(d) : "l"(a), "l"(b));
}

__device__ __forceinline__ float wred_sum(float v){
    #pragma unroll
    for(int o=16;o;o>>=1) v += __shfl_xor_sync(0xffffffffu, v, o);
    return v;
}
__device__ __forceinline__ float wred_max(float v){
    #pragma unroll
    for(int o=16;o;o>>=1) v = fmaxf(v, __shfl_xor_sync(0xffffffffu, v, o));
    return v;
}

// ============================================================================
// Kernel A: G[b] = X[b] * X[b]^T   (C x C, K = T), plus row sums s[b] = X.1
// X row-major [C][T]. Tiles 64x64, BK=32, 256 thr, 4x4 thread tile (f32x2).
// ============================================================================
__global__ __launch_bounds__(256) void k_xxT(const float* __restrict__ x,
                                             float* __restrict__ G,
                                             float* __restrict__ s)
{
    const int b  = blockIdx.z;
    const int m0 = blockIdx.y*64, n0 = blockIdx.x*64;
    __shared__ __align__(16) float As[32][68];
    __shared__ __align__(16) float Bs[32][68];
    __shared__ float ssm[64];
    const float* __restrict__ X = x + (size_t)b*CC*TT;
    const int tid = threadIdx.x;
    const int lr = tid>>3, lc = (tid&7)*4;      // tile load: row, col4
    const int tm = (tid>>4)*4, tn = (tid&15)*4; // compute: thread tile origin

    unsigned long long acc[4][2];
    #pragma unroll
    for(int i=0;i<4;i++){ acc[i][0]=0ull; acc[i][1]=0ull; }
    float sp0=0.f, sp1=0.f;
    const bool do_s = (blockIdx.x==0);
    if(tid<64) ssm[tid]=0.f;

    for(int k0=0;k0<TT;k0+=32){
        float4 a0 = *(const float4*)(X + (size_t)(m0+lr   )*TT + k0 + lc);
        float4 a1 = *(const float4*)(X + (size_t)(m0+lr+32)*TT + k0 + lc);
        float4 b0 = *(const float4*)(X + (size_t)(n0+lr   )*TT + k0 + lc);
        float4 b1 = *(const float4*)(X + (size_t)(n0+lr+32)*TT + k0 + lc);
        if(do_s){ sp0 += a0.x+a0.y+a0.z+a0.w; sp1 += a1.x+a1.y+a1.z+a1.w; }
        __syncthreads();
        As[lc+0][lr]=a0.x; As[lc+1][lr]=a0.y; As[lc+2][lr]=a0.z; As[lc+3][lr]=a0.w;
        As[lc+0][lr+32]=a1.x; As[lc+1][lr+32]=a1.y; As[lc+2][lr+32]=a1.z; As[lc+3][lr+32]=a1.w;
        Bs[lc+0][lr]=b0.x; Bs[lc+1][lr]=b0.y; Bs[lc+2][lr]=b0.z; Bs[lc+3][lr]=b0.w;
        Bs[lc+0][lr+32]=b1.x; Bs[lc+1][lr+32]=b1.y; Bs[lc+2][lr+32]=b1.z; Bs[lc+3][lr+32]=b1.w;
        __syncthreads();
        #pragma unroll
        for(int kk=0;kk<32;kk++){
            float4 af = *(const float4*)&As[kk][tm];
            float4 bf = *(const float4*)&Bs[kk][tn];
            unsigned long long b01 = pk2(bf.x,bf.y), b23 = pk2(bf.z,bf.w);
            unsigned long long ax = pk2(af.x,af.x), ay = pk2(af.y,af.y);
            unsigned long long az = pk2(af.z,af.z), aw = pk2(af.w,af.w);
            fma2(acc[0][0],ax,b01); fma2(acc[0][1],ax,b23);
            fma2(acc[1][0],ay,b01); fma2(acc[1][1],ay,b23);
            fma2(acc[2][0],az,b01); fma2(acc[2][1],az,b23);
            fma2(acc[3][0],aw,b01); fma2(acc[3][1],aw,b23);
        }
    }
    float* Gp = G + (size_t)b*CC*CC;
    #pragma unroll
    for(int i=0;i<4;i++){
        float4 o;
        upk2(acc[i][0], o.x, o.y);
        upk2(acc[i][1], o.z, o.w);
        *(float4*)(Gp + (size_t)(m0+tm+i)*CC + n0 + tn) = o;
    }
    if(do_s){
        atomicAdd(&ssm[lr], sp0);
        atomicAdd(&ssm[lr+32], sp1);
        __syncthreads();
        if(tid<64) s[(size_t)b*CC + m0 + tid] = ssm[tid];
    }
}

// ============================================================================
// Generic NN GEMM: Out[b] = A[b](MxK) * Bm[b](KxN) (+ addvec per row).
// A row-major stride K; Bm row-major stride N. Tiles 64x64, BK=32.
// ============================================================================
__global__ __launch_bounds__(256) void k_gemm_nn(
    const float* __restrict__ A, const float* __restrict__ Bm, float* __restrict__ Out,
    int N, int K, size_t strA, size_t strB, size_t strO,
    const float* __restrict__ addvec)
{
    const int b = blockIdx.z;
    const float* __restrict__ Ap = A + strA*(size_t)b;
    const float* __restrict__ Bp = Bm + strB*(size_t)b;
    float* __restrict__ Op = Out + strO*(size_t)b;
    const int m0 = blockIdx.y*64, n0 = blockIdx.x*64;
    __shared__ __align__(16) float As[32][68];
    __shared__ __align__(16) float Bs[32][68];
    const int tid = threadIdx.x;
    const int lr  = tid>>3, lc  = (tid&7)*4;   // A-tile load (transpose)
    const int lr2 = tid>>4, lc2 = (tid&15)*4;  // B-tile load (direct)
    const int tm  = (tid>>4)*4, tn = (tid&15)*4;

    unsigned long long acc[4][2];
    #pragma unroll
    for(int i=0;i<4;i++){ acc[i][0]=0ull; acc[i][1]=0ull; }

    for(int k0=0;k0<K;k0+=32){
        float4 a0 = *(const float4*)(Ap + (size_t)(m0+lr   )*K + k0 + lc);
        float4 a1 = *(const float4*)(Ap + (size_t)(m0+lr+32)*K + k0 + lc);
        float4 v0 = *(const float4*)(Bp + (size_t)(k0+lr2   )*N + n0 + lc2);
        float4 v1 = *(const float4*)(Bp + (size_t)(k0+lr2+16)*N + n0 + lc2);
        __syncthreads();
        As[lc+0][lr]=a0.x; As[lc+1][lr]=a0.y; As[lc+2][lr]=a0.z; As[lc+3][lr]=a0.w;
        As[lc+0][lr+32]=a1.x; As[lc+1][lr+32]=a1.y; As[lc+2][lr+32]=a1.z; As[lc+3][lr+32]=a1.w;
        *(float4*)&Bs[lr2][lc2]    = v0;
        *(float4*)&Bs[lr2+16][lc2] = v1;
        __syncthreads();
        #pragma unroll
        for(int kk=0;kk<32;kk++){
            float4 af = *(const float4*)&As[kk][tm];
            float4 bf = *(const float4*)&Bs[kk][tn];
            unsigned long long b01 = pk2(bf.x,bf.y), b23 = pk2(bf.z,bf.w);
            unsigned long long ax = pk2(af.x,af.x), ay = pk2(af.y,af.y);
            unsigned long long az = pk2(af.z,af.z), aw = pk2(af.w,af.w);
            fma2(acc[0][0],ax,b01); fma2(acc[0][1],ax,b23);
            fma2(acc[1][0],ay,b01); fma2(acc[1][1],ay,b23);
            fma2(acc[2][0],az,b01); fma2(acc[2][1],az,b23);
            fma2(acc[3][0],aw,b01); fma2(acc[3][1],aw,b23);
        }
    }
    #pragma unroll
    for(int i=0;i<4;i++){
        float4 o;
        upk2(acc[i][0], o.x, o.y);
        upk2(acc[i][1], o.z, o.w);
        if(addvec){
            float av = addvec[(size_t)b*CC + m0 + tm + i];
            o.x += av; o.y += av; o.z += av; o.w += av;
        }
        *(float4*)(Op + (size_t)(m0+tm+i)*N + n0 + tn) = o;
    }
}

// ============================================================================
// dots = H[b] * Wk^T  + rank-1 bias terms, scaled.  (NT GEMM, K=512)
// dots[c][d] = sum_e H[c][e]*Wk[d][e];  + u[c]*bk[d] + bq[c]*(w[d]+T*bk[d]); *SCALE
// ============================================================================
__global__ __launch_bounds__(256) void k_dots(
    const float* __restrict__ H, const float* __restrict__ Wk,
    float* __restrict__ dots,
    const float* __restrict__ u, const float* __restrict__ w,
    const float* __restrict__ bq, const float* __restrict__ bk)
{
    const int b = blockIdx.z;
    const float* __restrict__ Hp = H + (size_t)b*CC*CC;
    float* __restrict__ Dp = dots + (size_t)b*CC*CC;
    const int m0 = blockIdx.y*64, n0 = blockIdx.x*64;
    __shared__ __align__(16) float As[32][68];
    __shared__ __align__(16) float Bs[32][68];
    const int tid = threadIdx.x;
    const int lr = tid>>3, lc = (tid&7)*4;
    const int tm = (tid>>4)*4, tn = (tid&15)*4;

    unsigned long long acc[4][2];
    #pragma unroll
    for(int i=0;i<4;i++){ acc[i][0]=0ull; acc[i][1]=0ull; }

    for(int k0=0;k0<CC;k0+=32){
        float4 a0 = *(const float4*)(Hp + (size_t)(m0+lr   )*CC + k0 + lc);
        float4 a1 = *(const float4*)(Hp + (size_t)(m0+lr+32)*CC + k0 + lc);
        float4 b0 = *(const float4*)(Wk + (size_t)(n0+lr   )*CC + k0 + lc);
        float4 b1 = *(const float4*)(Wk + (size_t)(n0+lr+32)*CC + k0 + lc);
        __syncthreads();
        As[lc+0][lr]=a0.x; As[lc+1][lr]=a0.y; As[lc+2][lr]=a0.z; As[lc+3][lr]=a0.w;
        As[lc+0][lr+32]=a1.x; As[lc+1][lr+32]=a1.y; As[lc+2][lr+32]=a1.z; As[lc+3][lr+32]=a1.w;
        Bs[lc+0][lr]=b0.x; Bs[lc+1][lr]=b0.y; Bs[lc+2][lr]=b0.z; Bs[lc+3][lr]=b0.w;
        Bs[lc+0][lr+32]=b1.x; Bs[lc+1][lr+32]=b1.y; Bs[lc+2][lr+32]=b1.z; Bs[lc+3][lr+32]=b1.w;
        __syncthreads();
        #pragma unroll
        for(int kk=0;kk<32;kk++){
            float4 af = *(const float4*)&As[kk][tm];
            float4 bf = *(const float4*)&Bs[kk][tn];
            unsigned long long b01 = pk2(bf.x,bf.y), b23 = pk2(bf.z,bf.w);
            unsigned long long ax = pk2(af.x,af.x), ay = pk2(af.y,af.y);
            unsigned long long az = pk2(af.z,af.z), aw = pk2(af.w,af.w);
            fma2(acc[0][0],ax,b01); fma2(acc[0][1],ax,b23);
            fma2(acc[1][0],ay,b01); fma2(acc[1][1],ay,b23);
            fma2(acc[2][0],az,b01); fma2(acc[2][1],az,b23);
            fma2(acc[3][0],aw,b01); fma2(acc[3][1],aw,b23);
        }
    }
    float4 bk4 = *(const float4*)(bk + n0 + tn);
    float4 w4  = *(const float4*)(w + (size_t)b*CC + n0 + tn);
    #pragma unroll
    for(int i=0;i<4;i++){
        const int c = m0 + tm + i;
        float uc  = u[(size_t)b*CC + c];
        float bqc = bq[c];
        float4 o;
        upk2(acc[i][0], o.x, o.y);
        upk2(acc[i][1], o.z, o.w);
        o.x = (o.x + uc*bk4.x + bqc*(w4.x + 4096.0f*bk4.x)) * 0.125f;
        o.y = (o.y + uc*bk4.y + bqc*(w4.y + 4096.0f*bk4.y)) * 0.125f;
        o.z = (o.z + uc*bk4.z + bqc*(w4.z + 4096.0f*bk4.z)) * 0.125f;
        o.w = (o.w + uc*bk4.w + bqc*(w4.w + 4096.0f*bk4.w)) * 0.125f;
        *(float4*)(Dp + (size_t)c*CC + n0 + tn) = o;
    }
}

// ============================================================================
// u = Wq*s, w = Wk*s  (warp per output element)
// ============================================================================
__global__ __launch_bounds__(256) void k_uw(
    const float* __restrict__ Wq, const float* __restrict__ Wk,
    const float* __restrict__ s, float* __restrict__ u, float* __restrict__ w)
{
    const int b = blockIdx.z;
    const int which = blockIdx.y;
    const float* __restrict__ W = which ? Wk : Wq;
    const int o = blockIdx.x*8 + (threadIdx.x>>5);
    const int lane = threadIdx.x & 31;
    const float* __restrict__ sp = s + (size_t)b*CC;
    float acc = 0.f;
    #pragma unroll
    for(int it=0; it<4; it++){
        int c = lane*4 + it*128;
        float4 wv = *(const float4*)(W + (size_t)o*CC + c);
        float4 sv = *(const float4*)(sp + c);
        acc += wv.x*sv.x + wv.y*sv.y + wv.z*sv.z + wv.w*sv.w;
    }
    acc = wred_sum(acc);
    if(lane==0) (which ? w : u)[(size_t)b*CC + o] = acc;
}

// ============================================================================
// Row softmax (512 wide, warp per row) + fused rvec = attn . bv
// ============================================================================
__global__ __launch_bounds__(256) void k_softmax(
    const float* __restrict__ dots, float* __restrict__ attn,
    const float* __restrict__ bv, float* __restrict__ r)
{
    const int b = blockIdx.y;
    const int row = blockIdx.x*8 + (threadIdx.x>>5);
    const int lane = threadIdx.x & 31;
    const float* __restrict__ dr = dots + ((size_t)b*CC + row)*CC;
    float* __restrict__ ar = attn + ((size_t)b*CC + row)*CC;
    float v[16];
    float mx = -1e30f;
    #pragma unroll
    for(int it=0; it<4; it++){
        float4 t = *(const float4*)(dr + lane*4 + it*128);
        v[it*4+0]=t.x; v[it*4+1]=t.y; v[it*4+2]=t.z; v[it*4+3]=t.w;
        mx = fmaxf(mx, fmaxf(fmaxf(t.x,t.y), fmaxf(t.z,t.w)));
    }
    mx = wred_max(mx);
    float sum = 0.f;
    #pragma unroll
    for(int j=0;j<16;j++){ v[j] = expf(v[j]-mx); sum += v[j]; }
    sum = wred_sum(sum);
    const float inv = 1.f/sum;
    float rd = 0.f;
    #pragma unroll
    for(int it=0; it<4; it++){
        float4 bv4 = *(const float4*)(bv + lane*4 + it*128);
        float4 o;
        o.x = v[it*4+0]*inv; o.y = v[it*4+1]*inv;
        o.z = v[it*4+2]*inv; o.w = v[it*4+3]*inv;
        rd += o.x*bv4.x + o.y*bv4.y + o.z*bv4.z + o.w*bv4.w;
        *(float4*)(ar + lane*4 + it*128) = o;
    }
    rd = wred_sum(rd);
    if(lane==0) r[(size_t)b*CC + row] = rd;
}

// ============================================================================
extern "C" void kernel_launch(void* const* d_in, const int* in_sizes, int n_in,
                              void* d_out, int out_size)
{
    const float* x  = (const float*)d_in[0];
    const float* Wq = (const float*)d_in[1];
    const float* bq = (const float*)d_in[2];
    const float* Wk = (const float*)d_in[3];
    const float* bk = (const float*)d_in[4];
    const float* Wv = (const float*)d_in[5];
    const float* bv = (const float*)d_in[6];
    float* out = (float*)d_out;

    void* basep = nullptr;
    cudaGetSymbolAddress(&basep, g_scr);
    float* base = (float*)basep;
    const size_t MSZ = (size_t)BB*CC*CC;
    float* G    = base;
    float* H    = base + 1*MSZ;
    float* dots = base + 2*MSZ;
    float* attn = base + 3*MSZ;
    float* M    = base + 4*MSZ;
    float* s    = base + 5*MSZ;
    float* u    = s + BB*CC;
    float* w    = u + BB*CC;
    float* r    = w + BB*CC;

    dim3 blk(256,1,1);
    // 1) G = x x^T  (+ s row sums)
    k_xxT<<<dim3(CC/64, CC/64, BB), blk>>>(x, G, s);
    // 2) u = Wq s, w = Wk s
    k_uw<<<dim3(CC/8, 2, BB), blk>>>(Wq, Wk, s, u, w);
    // 3) H = Wq G
    k_gemm_nn<<<dim3(CC/64, CC/64, BB), blk>>>(Wq, G, H, CC, CC,
                                               0, MSZ? (size_t)CC*CC : 0, (size_t)CC*CC, nullptr);
    // 4) dots = H Wk^T + rank-1, scaled
    k_dots<<<dim3(CC/64, CC/64, BB), blk>>>(H, Wk, dots, u, w, bq, bk);
    // 5) softmax rows -> attn; rvec = attn . bv
    k_softmax<<<dim3(CC/8, BB), blk>>>(dots, attn, bv, r);
    // 6) M = attn Wv
    k_gemm_nn<<<dim3(CC/64, CC/64, BB), blk>>>(attn, Wv, M, CC, CC,
                                               (size_t)CC*CC, 0, (size_t)CC*CC, nullptr);
    // 7) out = M x + rvec
    k_gemm_nn<<<dim3(TT/64, CC/64, BB), blk>>>(M, x, out, TT, CC,
                                               (size_t)CC*CC, (size_t)CC*TT, (size_t)CC*TT, r);
}

// round 4
// speedup vs baseline: 2.2027x; 2.2027x over previous
#include <cuda_runtime.h>
#include <cuda_fp16.h>
#include <math.h>
#include <stdint.h>

#define BB 8
#define CC 512
#define TT 4096

// xh,xl,xth,xtl: 4*32MB=128MB; W splits ~3MB; G/H/M/attn hi+lo 32MB; dots 8MB; vecs
static __device__ __align__(256) unsigned char g_scr[184u*1024u*1024u];

// ============================ helpers =======================================
__device__ __forceinline__ uint32_t smem_u32(const void* p){
    uint32_t a;
    asm("{ .reg .u64 t; cvta.to.shared.u64 t, %1; cvt.u32.u64 %0, t; }" : "=r"(a) : "l"(p));
    return a;
}
__device__ __forceinline__ void cpa16(uint32_t s, const void* g){
    asm volatile("cp.async.cg.shared.global [%0], [%1], 16;" :: "r"(s), "l"(g));
}
__device__ __forceinline__ void cpa_commit(){ asm volatile("cp.async.commit_group;" ::: "memory"); }
template<int N> __device__ __forceinline__ void cpa_wait(){
    asm volatile("cp.async.wait_group %0;" :: "n"(N) : "memory");
}
__device__ __forceinline__ void ldsm4(uint32_t* r, uint32_t addr){
    asm volatile("ldmatrix.sync.aligned.m8n8.x4.shared.b16 {%0,%1,%2,%3}, [%4];"
        : "=r"(r[0]), "=r"(r[1]), "=r"(r[2]), "=r"(r[3]) : "r"(addr));
}
__device__ __forceinline__ void mma16816(float* d, const uint32_t* a, uint32_t b0, uint32_t b1){
    asm volatile("mma.sync.aligned.m16n8k16.row.col.f32.f16.f16.f32 "
        "{%0,%1,%2,%3}, {%4,%5,%6,%7}, {%8,%9}, {%0,%1,%2,%3};"
        : "+f"(d[0]), "+f"(d[1]), "+f"(d[2]), "+f"(d[3])
        : "r"(a[0]), "r"(a[1]), "r"(a[2]), "r"(a[3]), "r"(b0), "r"(b1));
}
__device__ __forceinline__ void split2h(float f, __half &h, __half &l){
    h = __float2half_rn(f);
    l = __float2half_rn(f - __half2float(h));
}
__device__ __forceinline__ float wred_sum(float v){
    #pragma unroll
    for(int o=16;o;o>>=1) v += __shfl_xor_sync(0xffffffffu, v, o);
    return v;
}
__device__ __forceinline__ float wred_max(float v){
    #pragma unroll
    for(int o=16;o;o>>=1) v = fmaxf(v, __shfl_xor_sync(0xffffffffu, v, o));
    return v;
}

// ============================================================================
// Split/transpose x: xh,xl [b,c,t]; xth,xtl [b,t,c]; s[b,c] += rowsum
// ============================================================================
__global__ __launch_bounds__(256) void k_split_x(
    const float* __restrict__ x,
    __half* __restrict__ xh, __half* __restrict__ xl,
    __half* __restrict__ xth, __half* __restrict__ xtl,
    float* __restrict__ s)
{
    __shared__ float tile[32][129];
    const int b = blockIdx.z;
    const int t0 = blockIdx.x*128, c0 = blockIdx.y*32;
    const int tx = threadIdx.x & 31, ty = threadIdx.x >> 5;
    #pragma unroll
    for(int i=0;i<4;i++){
        const int cl = ty + 8*i;
        const int c = c0 + cl;
        float4 v = *(const float4*)(x + ((size_t)b*CC + c)*TT + t0 + tx*4);
        __align__(8) __half hv[4], lv[4];
        split2h(v.x,hv[0],lv[0]); split2h(v.y,hv[1],lv[1]);
        split2h(v.z,hv[2],lv[2]); split2h(v.w,hv[3],lv[3]);
        size_t o = ((size_t)b*CC + c)*TT + t0 + tx*4;
        *(uint2*)(xh+o) = *(uint2*)hv;
        *(uint2*)(xl+o) = *(uint2*)lv;
        tile[cl][tx*4+0]=v.x; tile[cl][tx*4+1]=v.y;
        tile[cl][tx*4+2]=v.z; tile[cl][tx*4+3]=v.w;
        float rs = wred_sum(v.x+v.y+v.z+v.w);
        if(tx==0) atomicAdd(&s[(size_t)b*CC + c], rs);
    }
    __syncthreads();
    const int r = threadIdx.x>>1, h = threadIdx.x&1;
    __align__(16) __half hv[16], lv[16];
    #pragma unroll
    for(int j=0;j<16;j++) split2h(tile[h*16+j][r], hv[j], lv[j]);
    size_t ob = ((size_t)b*TT + t0 + r)*CC + c0 + h*16;
    *(uint4*)(xth+ob)   = *(uint4*)hv;  *(uint4*)(xth+ob+8) = *(uint4*)(hv+8);
    *(uint4*)(xtl+ob)   = *(uint4*)lv;  *(uint4*)(xtl+ob+8) = *(uint4*)(lv+8);
}

// elementwise split: Wq (y=0) / Wk (y=1)
__global__ __launch_bounds__(256) void k_split_w(
    const float* __restrict__ Wq, const float* __restrict__ Wk,
    __half* __restrict__ qh, __half* __restrict__ ql,
    __half* __restrict__ kh, __half* __restrict__ kl)
{
    const int which = blockIdx.y;
    const float* W = which ? Wk : Wq;
    __half* oh = which ? kh : qh;
    __half* ol = which ? kl : ql;
    size_t i = ((size_t)blockIdx.x*256 + threadIdx.x)*4;
    float4 v = *(const float4*)(W + i);
    __align__(8) __half hv[4], lv[4];
    split2h(v.x,hv[0],lv[0]); split2h(v.y,hv[1],lv[1]);
    split2h(v.z,hv[2],lv[2]); split2h(v.w,hv[3],lv[3]);
    *(uint2*)(oh+i) = *(uint2*)hv;
    *(uint2*)(ol+i) = *(uint2*)lv;
}

// transpose-split Wv -> WvT[o][d] = Wv[d][o]
__global__ __launch_bounds__(256) void k_split_wT(
    const float* __restrict__ Wv, __half* __restrict__ th, __half* __restrict__ tl)
{
    __shared__ float tile[32][129];
    const int o0 = blockIdx.x*128, d0 = blockIdx.y*32;
    const int tx = threadIdx.x & 31, ty = threadIdx.x >> 5;
    #pragma unroll
    for(int i=0;i<4;i++){
        const int dl = ty + 8*i;
        float4 v = *(const float4*)(Wv + (size_t)(d0+dl)*CC + o0 + tx*4);
        tile[dl][tx*4+0]=v.x; tile[dl][tx*4+1]=v.y;
        tile[dl][tx*4+2]=v.z; tile[dl][tx*4+3]=v.w;
    }
    __syncthreads();
    const int r = threadIdx.x>>1, h = threadIdx.x&1;
    __align__(16) __half hv[16], lv[16];
    #pragma unroll
    for(int j=0;j<16;j++) split2h(tile[h*16+j][r], hv[j], lv[j]);
    size_t ob = (size_t)(o0 + r)*CC + d0 + h*16;
    *(uint4*)(th+ob)   = *(uint4*)hv;  *(uint4*)(th+ob+8) = *(uint4*)(hv+8);
    *(uint4*)(tl+ob)   = *(uint4*)lv;  *(uint4*)(tl+ob+8) = *(uint4*)(lv+8);
}

// u = Wq*s, w = Wk*s
__global__ __launch_bounds__(256) void k_uw(
    const float* __restrict__ Wq, const float* __restrict__ Wk,
    const float* __restrict__ s, float* __restrict__ u, float* __restrict__ w)
{
    const int b = blockIdx.z;
    const int which = blockIdx.y;
    const float* __restrict__ W = which ? Wk : Wq;
    const int o = blockIdx.x*8 + (threadIdx.x>>5);
    const int lane = threadIdx.x & 31;
    const float* __restrict__ sp = s + (size_t)b*CC;
    float acc = 0.f;
    #pragma unroll
    for(int it=0; it<4; it++){
        int c = lane*4 + it*128;
        float4 wv = *(const float4*)(W + (size_t)o*CC + c);
        float4 sv = *(const float4*)(sp + c);
        acc += wv.x*sv.x + wv.y*sv.y + wv.z*sv.z + wv.w*sv.w;
    }
    acc = wred_sum(acc);
    if(lane==0) (which ? w : u)[(size_t)b*CC + o] = acc;
}

// row softmax over 512 + split attn -> ah,al (fp16); r = attn . bv
__global__ __launch_bounds__(256) void k_softmax(
    const float* __restrict__ dots,
    __half* __restrict__ ah, __half* __restrict__ al,
    const float* __restrict__ bv, float* __restrict__ r)
{
    const int b = blockIdx.y;
    const int row = blockIdx.x*8 + (threadIdx.x>>5);
    const int lane = threadIdx.x & 31;
    const float* __restrict__ dr = dots + ((size_t)b*CC + row)*CC;
    float v[16];
    float mx = -1e30f;
    #pragma unroll
    for(int it=0; it<4; it++){
        float4 t = *(const float4*)(dr + lane*4 + it*128);
        v[it*4+0]=t.x; v[it*4+1]=t.y; v[it*4+2]=t.z; v[it*4+3]=t.w;
        mx = fmaxf(mx, fmaxf(fmaxf(t.x,t.y), fmaxf(t.z,t.w)));
    }
    mx = wred_max(mx);
    float sum = 0.f;
    #pragma unroll
    for(int j=0;j<16;j++){ v[j] = expf(v[j]-mx); sum += v[j]; }
    sum = wred_sum(sum);
    const float inv = 1.f/sum;
    float rd = 0.f;
    size_t rb = ((size_t)b*CC + row)*CC;
    #pragma unroll
    for(int it=0; it<4; it++){
        float4 bv4 = *(const float4*)(bv + lane*4 + it*128);
        float a0=v[it*4+0]*inv, a1=v[it*4+1]*inv, a2=v[it*4+2]*inv, a3=v[it*4+3]*inv;
        rd += a0*bv4.x + a1*bv4.y + a2*bv4.z + a3*bv4.w;
        __align__(8) __half hv[4], lv[4];
        split2h(a0,hv[0],lv[0]); split2h(a1,hv[1],lv[1]);
        split2h(a2,hv[2],lv[2]); split2h(a3,hv[3],lv[3]);
        size_t o = rb + lane*4 + it*128;
        *(uint2*)(ah+o) = *(uint2*)hv;
        *(uint2*)(al+o) = *(uint2*)lv;
    }
    rd = wred_sum(rd);
    if(lane==0) r[(size_t)b*CC + row] = rd;
}

// ============================================================================
// fp16x2 (3-product) NT GEMM on mma.sync: D[m][n] = sum_k A[m][k]*B[n][k]
// BM=BN=128, BK=32. SMEM rows padded to 80B (conflict-free ldmatrix).
// cp.async double-buffered. modes: 0 -> split fp16 hi/lo; 1 -> dots; 2 -> +r
// ============================================================================
#define TILE_B 10240            // 128 rows * 80B
#define STG_B  40960            // 4 tiles (Ah,Al,Bh,Bl)
#define SMEM_MMA (2*STG_B)

__global__ __launch_bounds__(256) void k_wmma_nt(
    const __half* __restrict__ Ah, const __half* __restrict__ Al, size_t strA,
    const __half* __restrict__ Bh, const __half* __restrict__ Bl, size_t strB,
    int K, void* out1, void* out2, size_t strO, int ldo, int mode,
    const float* __restrict__ vu, const float* __restrict__ vw,
    const float* __restrict__ vbq, const float* __restrict__ vbk,
    const float* __restrict__ vr)
{
    extern __shared__ __align__(128) unsigned char smem[];
    const uint32_t sb = smem_u32(smem);
    const int tid = threadIdx.x, lane = tid&31, wid = tid>>5;
    const int b = blockIdx.z;
    const int m0 = blockIdx.y*128, n0 = blockIdx.x*128;

    // ---- loaders: thread -> (row, 32B half-row) ----
    const int r = tid>>1, h = tid&1;
    const __half* gA0 = Ah + strA*b + (size_t)(m0+r)*K + h*16;
    const __half* gA1 = Al + strA*b + (size_t)(m0+r)*K + h*16;
    const __half* gB0 = Bh + strB*b + (size_t)(n0+r)*K + h*16;
    const __half* gB1 = Bl + strB*b + (size_t)(n0+r)*K + h*16;
    const uint32_t sdst = sb + (uint32_t)(r*80 + h*32);

    const int nch = K/32;
    // prologue: stage 0
    {
        cpa16(sdst,            gA0); cpa16(sdst+16,          gA0+8);
        cpa16(sdst+TILE_B,     gA1); cpa16(sdst+TILE_B+16,   gA1+8);
        cpa16(sdst+2*TILE_B,   gB0); cpa16(sdst+2*TILE_B+16, gB0+8);
        cpa16(sdst+3*TILE_B,   gB1); cpa16(sdst+3*TILE_B+16, gB1+8);
        cpa_commit();
    }

    const int wm = wid&1, wn = wid>>1;
    const int lr16 = lane&15, lkc = lane>>4;
    float acc[4][4][4];
    #pragma unroll
    for(int i=0;i<4;i++)
        #pragma unroll
        for(int j=0;j<4;j++){ acc[i][j][0]=0.f; acc[i][j][1]=0.f; acc[i][j][2]=0.f; acc[i][j][3]=0.f; }

    for(int c=0;c<nch;c++){
        if(c+1 < nch){
            const uint32_t s = sdst + (uint32_t)((c+1)&1)*STG_B;
            const size_t ko = (size_t)(c+1)*32;
            cpa16(s,            gA0+ko); cpa16(s+16,          gA0+ko+8);
            cpa16(s+TILE_B,     gA1+ko); cpa16(s+TILE_B+16,   gA1+ko+8);
            cpa16(s+2*TILE_B,   gB0+ko); cpa16(s+2*TILE_B+16, gB0+ko+8);
            cpa16(s+3*TILE_B,   gB1+ko); cpa16(s+3*TILE_B+16, gB1+ko+8);
            cpa_commit();
            cpa_wait<1>();
        } else {
            cpa_wait<0>();
        }
        __syncthreads();
        const uint32_t sbase = sb + (uint32_t)(c&1)*STG_B;
        #pragma unroll
        for(int ks=0; ks<2; ks++){
            const uint32_t coff = (uint32_t)((ks*2 + lkc)*16);
            uint32_t ahf[4][4], alf[4][4], bhf[2][4], blf[2][4];
            #pragma unroll
            for(int mt=0; mt<4; mt++){
                const uint32_t a = sbase + (uint32_t)((wm*64 + mt*16 + lr16)*80) + coff;
                ldsm4(ahf[mt], a);
                ldsm4(alf[mt], a + TILE_B);
            }
            #pragma unroll
            for(int nt2=0; nt2<2; nt2++){
                const uint32_t a = sbase + 2*TILE_B + (uint32_t)((wn*32 + nt2*16 + lr16)*80) + coff;
                ldsm4(bhf[nt2], a);
                ldsm4(blf[nt2], a + TILE_B);
            }
            #pragma unroll
            for(int mt=0; mt<4; mt++){
                #pragma unroll
                for(int nt=0; nt<4; nt++){
                    const int n2 = nt>>1, p = nt&1;
                    float* d = acc[mt][nt];
                    mma16816(d, ahf[mt], bhf[n2][p], bhf[n2][p+2]);   // hi*hi
                    mma16816(d, ahf[mt], blf[n2][p], blf[n2][p+2]);   // hi*lo
                    mma16816(d, alf[mt], bhf[n2][p], bhf[n2][p+2]);   // lo*hi
                }
            }
        }
        __syncthreads();
    }

    // ---- epilogue: direct fragment writeout ----
    const int mW = m0 + wm*64, nW = n0 + wn*32;
    const int er = lane>>2, ec = (lane&3)*2;
    if(mode == 0){
        __half* oH = (__half*)out1 + strO*b;
        __half* oL = (__half*)out2 + strO*b;
        #pragma unroll
        for(int mt=0; mt<4; mt++){
            const int m = mW + mt*16 + er;
            #pragma unroll
            for(int nt=0; nt<4; nt++){
                const int n = nW + nt*8 + ec;
                const float* d = acc[mt][nt];
                __half h0,l0,h1,l1;
                split2h(d[0],h0,l0); split2h(d[1],h1,l1);
                *(__half2*)(oH + (size_t)m*ldo + n) = __halves2half2(h0,h1);
                *(__half2*)(oL + (size_t)m*ldo + n) = __halves2half2(l0,l1);
                split2h(d[2],h0,l0); split2h(d[3],h1,l1);
                *(__half2*)(oH + (size_t)(m+8)*ldo + n) = __halves2half2(h0,h1);
                *(__half2*)(oL + (size_t)(m+8)*ldo + n) = __halves2half2(l0,l1);
            }
        }
    } else if(mode == 1){
        float* oF = (float*)out1 + strO*b;
        #pragma unroll
        for(int mt=0; mt<4; mt++){
            const int m = mW + mt*16 + er;
            const float u0 = vu[(size_t)b*CC + m],   u1 = vu[(size_t)b*CC + m + 8];
            const float q0 = vbq[m],                 q1 = vbq[m + 8];
            #pragma unroll
            for(int nt=0; nt<4; nt++){
                const int n = nW + nt*8 + ec;
                const float2 bk2 = *(const float2*)(vbk + n);
                const float2 w2  = *(const float2*)(vw + (size_t)b*CC + n);
                const float t0 = w2.x + 4096.0f*bk2.x, t1 = w2.y + 4096.0f*bk2.y;
                const float* d = acc[mt][nt];
                float2 o0, o1;
                o0.x = (d[0] + u0*bk2.x + q0*t0)*0.125f;
                o0.y = (d[1] + u0*bk2.y + q0*t1)*0.125f;
                o1.x = (d[2] + u1*bk2.x + q1*t0)*0.125f;
                o1.y = (d[3] + u1*bk2.y + q1*t1)*0.125f;
                *(float2*)(oF + (size_t)m*ldo + n)     = o0;
                *(float2*)(oF + (size_t)(m+8)*ldo + n) = o1;
            }
        }
    } else {
        float* oF = (float*)out1 + strO*b;
        #pragma unroll
        for(int mt=0; mt<4; mt++){
            const int m = mW + mt*16 + er;
            const float r0 = vr[(size_t)b*CC + m], r1 = vr[(size_t)b*CC + m + 8];
            #pragma unroll
            for(int nt=0; nt<4; nt++){
                const int n = nW + nt*8 + ec;
                const float* d = acc[mt][nt];
                float2 o0, o1;
                o0.x = d[0]+r0; o0.y = d[1]+r0;
                o1.x = d[2]+r1; o1.y = d[3]+r1;
                *(float2*)(oF + (size_t)m*ldo + n)     = o0;
                *(float2*)(oF + (size_t)(m+8)*ldo + n) = o1;
            }
        }
    }
}

// ============================================================================
extern "C" void kernel_launch(void* const* d_in, const int* in_sizes, int n_in,
                              void* d_out, int out_size)
{
    const float* x  = (const float*)d_in[0];
    const float* Wq = (const float*)d_in[1];
    const float* bq = (const float*)d_in[2];
    const float* Wk = (const float*)d_in[3];
    const float* bk = (const float*)d_in[4];
    const float* Wv = (const float*)d_in[5];
    const float* bv = (const float*)d_in[6];
    float* out = (float*)d_out;

    void* basep = nullptr;
    cudaGetSymbolAddress(&basep, g_scr);
    unsigned char* base = (unsigned char*)basep;

    const size_t XE = (size_t)BB*CC*TT;
    const size_t WE = (size_t)CC*CC;
    const size_t GE = (size_t)BB*CC*CC;
    size_t off = 0;
    auto take = [&](size_t bytes){ size_t o = off; off += (bytes + 255) & ~(size_t)255; return o; };
    __half* xh  = (__half*)(base + take(XE*2));
    __half* xl  = (__half*)(base + take(XE*2));
    __half* xth = (__half*)(base + take(XE*2));
    __half* xtl = (__half*)(base + take(XE*2));
    __half* wqh = (__half*)(base + take(WE*2));
    __half* wql = (__half*)(base + take(WE*2));
    __half* wkh = (__half*)(base + take(WE*2));
    __half* wkl = (__half*)(base + take(WE*2));
    __half* wvth= (__half*)(base + take(WE*2));
    __half* wvtl= (__half*)(base + take(WE*2));
    __half* Gh  = (__half*)(base + take(GE*2));
    __half* Gl  = (__half*)(base + take(GE*2));
    __half* Hh  = (__half*)(base + take(GE*2));
    __half* Hl  = (__half*)(base + take(GE*2));
    __half* Mh  = (__half*)(base + take(GE*2));
    __half* Ml  = (__half*)(base + take(GE*2));
    __half* ah  = (__half*)(base + take(GE*2));
    __half* al  = (__half*)(base + take(GE*2));
    float* dots = (float*)(base + take(GE*4));
    float* s    = (float*)(base + take((size_t)BB*CC*4));
    float* u    = (float*)(base + take((size_t)BB*CC*4));
    float* w    = (float*)(base + take((size_t)BB*CC*4));
    float* rr   = (float*)(base + take((size_t)BB*CC*4));

    cudaFuncSetAttribute(k_wmma_nt, cudaFuncAttributeMaxDynamicSharedMemorySize, SMEM_MMA);
    cudaMemsetAsync(s, 0, (size_t)BB*CC*4);

    dim3 blk(256,1,1);
    k_split_x<<<dim3(TT/128, CC/32, BB), blk>>>(x, xh, xl, xth, xtl, s);
    k_split_w<<<dim3(CC*CC/1024, 2, 1), blk>>>(Wq, Wk, wqh, wql, wkh, wkl);
    k_split_wT<<<dim3(CC/128, CC/32, 1), blk>>>(Wv, wvth, wvtl);
    k_uw<<<dim3(CC/8, 2, BB), blk>>>(Wq, Wk, s, u, w);
    // G = x x^T (mode 0 -> Gh,Gl)
    k_wmma_nt<<<dim3(CC/128, CC/128, BB), blk, SMEM_MMA>>>(
        xh, xl, (size_t)CC*TT, xh, xl, (size_t)CC*TT, TT,
        Gh, Gl, (size_t)CC*CC, CC, 0, nullptr,nullptr,nullptr,nullptr,nullptr);
    // H = Wq G (G symmetric -> NT)
    k_wmma_nt<<<dim3(CC/128, CC/128, BB), blk, SMEM_MMA>>>(
        wqh, wql, (size_t)0, Gh, Gl, (size_t)CC*CC, CC,
        Hh, Hl, (size_t)CC*CC, CC, 0, nullptr,nullptr,nullptr,nullptr,nullptr);
    // dots = H Wk^T + rank-1, scaled (mode 1, fp32)
    k_wmma_nt<<<dim3(CC/128, CC/128, BB), blk, SMEM_MMA>>>(
        Hh, Hl, (size_t)CC*CC, wkh, wkl, (size_t)0, CC,
        dots, nullptr, (size_t)CC*CC, CC, 1, u, w, bq, bk, nullptr);
    // softmax -> ah,al ; r = attn.bv
    k_softmax<<<dim3(CC/8, BB), blk>>>(dots, ah, al, bv, rr);
    // M = attn Wv (NT with WvT)
    k_wmma_nt<<<dim3(CC/128, CC/128, BB), blk, SMEM_MMA>>>(
        ah, al, (size_t)CC*CC, wvth, wvtl, (size_t)0, CC,
        Mh, Ml, (size_t)CC*CC, CC, 0, nullptr,nullptr,nullptr,nullptr,nullptr);
    // out = M x + r (NT with xT; mode 2, fp32, ldo=T)
    k_wmma_nt<<<dim3(TT/128, CC/128, BB), blk, SMEM_MMA>>>(
        Mh, Ml, (size_t)CC*CC, xth, xtl, (size_t)TT*CC, CC,
        out, nullptr, (size_t)CC*TT, TT, 2, nullptr,nullptr,nullptr,nullptr, rr);
}